// round 16
// baseline (speedup 1.0000x reference)
#include <cuda_runtime.h>
#include <math.h>

#define NEG        (-1.0e9f)
#define SCORE_TH   (0.05f)
#define MAXDET     100

#define NBINS1     1024               // (bits>>16)-MINB16; score 1.0 -> bin 564
#define NBINS2     512                // bits[7:16) within one level-1 bin
#define MINB16     15692              // bits(0.05f) >> 16
#define KCAP       256                // candidate capacity (select & topk)
#define TARGET     160                // select candidate target (>= MAXDET + margin)
#define SB         512                // select block
#define TROWS      32                 // transpose tile rows
#define XB         256                // transpose block

#define MAXB       4
#define MAXC       96
#define MAXN       10240

__device__ float        g_tcls[MAXB * MAXC * MAXN];   // (B,C,N) transposed scores
__device__ float        g_sc[MAXB * MAXC * MAXDET];
__device__ float4       g_bx[MAXB * MAXC * MAXDET];
__device__ int          g_flag[MAXB * MAXC];
__device__ unsigned int g_ticket[MAXB];               // monotonic across replays

__device__ __forceinline__ unsigned long long packKey(float s, unsigned idx) {
    unsigned u = __float_as_uint(s);
    u = (u & 0x80000000u) ? ~u : (u | 0x80000000u);
    return ((unsigned long long)u << 32) | (unsigned)(~idx);
}
__device__ __forceinline__ float keyScore(unsigned long long k) {
    unsigned u = (unsigned)(k >> 32);
    u = (u & 0x80000000u) ? (u & 0x7FFFFFFFu) : ~u;
    return __uint_as_float(u);
}
__device__ __forceinline__ unsigned keyIdx(unsigned long long k) {
    return ~(unsigned)(k & 0xFFFFFFFFu);
}
// exact equivalent of RN(inter/u) > 0.5 for u >= ~1 (areas >= 1 here)
__device__ __forceinline__ bool iouGtHalf(float inter, float u) {
    return fmaf(-0.5f, u, inter) > 2.9802322387695312e-08f * u;
}
__device__ __forceinline__ int binOf1(float sc) {   // sc > 0.05
    int b = (int)(__float_as_uint(sc) >> 16) - MINB16;
    return b > (NBINS1 - 1) ? (NBINS1 - 1) : b;
}
__device__ __forceinline__ int binOf2(float sc) {
    return (int)((__float_as_uint(sc) >> 7) & 0x1FFu);
}

// ---- 512-thread helpers ----
__device__ __forceinline__ void suffix1024_512(int* S, int* wsum, int* wafter,
                                               int t, int lane, int wid) {
    int b0 = S[2 * t], b1 = S[2 * t + 1];
    int s = b0 + b1;
    #pragma unroll
    for (int o = 1; o < 32; o <<= 1) {
        int u = __shfl_down_sync(0xFFFFFFFFu, s, o);
        if (lane + o < 32) s += u;
    }
    if (lane == 0) wsum[wid] = s;
    __syncthreads();
    if (t < 32) {
        int v = (t < 16) ? wsum[t] : 0;
        #pragma unroll
        for (int o = 1; o < 16; o <<= 1) {
            int u = __shfl_down_sync(0xFFFFFFFFu, v, o);
            if (t + o < 16) v += u;
        }
        if (t < 16) wafter[t] = v - wsum[t];
    }
    __syncthreads();
    int T = s + wafter[wid];
    S[2 * t] = T;
    S[2 * t + 1] = T - b0;
    __syncthreads();
}
__device__ __forceinline__ void suffix512_512(int* S2, int* wsum, int* wafter,
                                              int t, int lane, int wid) {
    int s = S2[t];
    #pragma unroll
    for (int o = 1; o < 32; o <<= 1) {
        int u = __shfl_down_sync(0xFFFFFFFFu, s, o);
        if (lane + o < 32) s += u;
    }
    if (lane == 0) wsum[wid] = s;
    __syncthreads();
    if (t < 32) {
        int v = (t < 16) ? wsum[t] : 0;
        #pragma unroll
        for (int o = 1; o < 16; o <<= 1) {
            int u = __shfl_down_sync(0xFFFFFFFFu, v, o);
            if (t + o < 16) v += u;
        }
        if (t < 16) wafter[t] = v - wsum[t];
    }
    __syncthreads();
    S2[t] = s + wafter[wid];
    __syncthreads();
}
__device__ __forceinline__ unsigned long long blockKeyMax512(unsigned long long k,
                                                             unsigned long long* red) {
    int lane = threadIdx.x & 31;
    int wid  = threadIdx.x >> 5;
    #pragma unroll
    for (int o = 16; o > 0; o >>= 1) {
        unsigned long long other = __shfl_down_sync(0xFFFFFFFFu, k, o);
        if (other > k) k = other;
    }
    if (lane == 0) red[wid] = k;
    __syncthreads();
    if (wid == 0) {
        unsigned long long v = red[lane & 15];
        #pragma unroll
        for (int o = 8; o > 0; o >>= 1) {
            unsigned long long other = __shfl_down_sync(0xFFFFFFFFu, v, o);
            if (other > v) v = other;
        }
        if (lane == 0) red[16] = v;
    }
    __syncthreads();
    unsigned long long r = red[16];
    __syncthreads();
    return r;
}

// ======= Kernel 0: transpose (B,N,C)->(B,C,N), float4 both sides =============
__global__ void __launch_bounds__(XB)
transpose_kernel(const float* __restrict__ cls, int N, int C) {
    extern __shared__ float tile[];                 // TROWS * RS floats, RS odd
    const int RS = C | 1;
    const int b  = blockIdx.y;
    const int i0 = blockIdx.x * TROWS;
    const int t  = threadIdx.x;
    int rows = N - i0; if (rows > TROWS) rows = TROWS;
    const int n_e = rows * C;
    const float* src = cls + (size_t)b * N * C + (size_t)i0 * C;

    if ((C & 3) == 0) {
        const float4* s4 = (const float4*)src;
        const int n4 = n_e >> 2;
        const int C4 = C >> 2;
        for (int e = t; e < n4; e += XB) {
            float4 v = s4[e];
            int r = e / C4, c0 = (e - r * C4) << 2;
            float* dst = tile + r * RS + c0;
            dst[0] = v.x; dst[1] = v.y; dst[2] = v.z; dst[3] = v.w;
        }
    } else {
        for (int e = t; e < n_e; e += XB) {
            int r = e / C, c = e - r * C;
            tile[r * RS + c] = src[e];
        }
    }
    __syncthreads();

    const int r4cnt = rows >> 2;
    const int n_out4 = C * r4cnt;
    for (int e = t; e < n_out4; e += XB) {
        int c2  = e / r4cnt;
        int rr4 = e - c2 * r4cnt;
        int r0 = rr4 << 2;
        const float* srcw = tile + r0 * RS + c2;
        float4 v;
        v.x = srcw[0];
        v.y = srcw[RS];
        v.z = srcw[2 * RS];
        v.w = srcw[3 * RS];
        *(float4*)&g_tcls[((size_t)(b * MAXC + c2)) * MAXN + i0 + r0] = v;
    }
    const int rrem0 = r4cnt << 2;
    if (rrem0 < rows) {
        const int n_rem = C * (rows - rrem0);
        for (int e = t; e < n_rem; e += XB) {
            int c = e / (rows - rrem0), r = rrem0 + (e - c * (rows - rrem0));
            g_tcls[((size_t)(b * MAXC + c)) * MAXN + i0 + r] = tile[r * RS + c];
        }
    }
}

// == Kernel 1: select + bitmask NMS, then ticketed per-image topk =============
__global__ void __launch_bounds__(SB, 2)
select_nms_kernel(const float4* __restrict__ boxes, float* __restrict__ out,
                  int N, int C, int B) {
    extern __shared__ float       scache[];          // N floats (score cache)
    __shared__ int                S[NBINS1];
    __shared__ int                S2[NBINS2];
    __shared__ unsigned long long key[KCAP];
    __shared__ unsigned long long skey[KCAP];
    __shared__ float4             cbox[KCAP];
    __shared__ float              carea[KCAP];
    __shared__ unsigned           suppRow[KCAP][KCAP / 32];   // 8 KB
    __shared__ short              keptIdx[MAXDET];
    __shared__ int                wsum[16], wafter[16];
    __shared__ unsigned long long red[17];
    __shared__ int                s_piv1, s_piv2, s_ctr, s_kept, s_last;

    const int c = blockIdx.x;
    const int b = blockIdx.y;
    const int t = threadIdx.x;
    const int lane = t & 31, wid = t >> 5;
    const int bc = b * C + c;
    const int base = bc * MAXDET;
    const float*  cp  = g_tcls + ((size_t)(b * MAXC + c)) * MAXN;
    const float4* cp4 = (const float4*)cp;
    const float4* bp  = boxes + (size_t)b * N;
    float4* sc4 = (float4*)scache;
    const int N4 = N >> 2;

    bool doneEarly = false;

    S[2 * t] = 0; S[2 * t + 1] = 0; S2[t] = 0;
    if (t < KCAP) { key[t] = 0ULL; skey[t] = 0ULL; }
    if (t == 0) { s_ctr = 0; g_flag[bc] = 0; }
    __syncthreads();

    for (int i = t; i < N4; i += SB) {
        float4 v = cp4[i];
        sc4[i] = v;
        if (v.x > SCORE_TH) atomicAdd(&S[binOf1(v.x)], 1);
        if (v.y > SCORE_TH) atomicAdd(&S[binOf1(v.y)], 1);
        if (v.z > SCORE_TH) atomicAdd(&S[binOf1(v.z)], 1);
        if (v.w > SCORE_TH) atomicAdd(&S[binOf1(v.w)], 1);
    }
    for (int i = 4 * N4 + t; i < N; i += SB) {
        float v = cp[i];
        scache[i] = v;
        if (v > SCORE_TH) atomicAdd(&S[binOf1(v)], 1);
    }
    __syncthreads();
    suffix1024_512(S, wsum, wafter, t, lane, wid);

    const int total = S[0];
    if (total == 0) {
        for (int mm = t; mm < MAXDET; mm += SB) g_sc[base + mm] = NEG;
        doneEarly = true;
    }

    if (!doneEarly) {
        const int target = total < TARGET ? total : TARGET;
        #pragma unroll
        for (int h = 0; h < 2; h++) {
            int p = t + h * SB;
            if (S[p] >= target && (p == NBINS1 - 1 || S[p + 1] < target)) s_piv1 = p;
        }
        __syncthreads();
        const int piv1 = s_piv1;
        const int cnt1 = S[piv1];
        const int above = (piv1 + 1 < NBINS1) ? S[piv1 + 1] : 0;
        const bool use2 = (cnt1 > KCAP);
        int piv2 = 0;
        int cnt  = cnt1;

        if (use2) {
            for (int i = t; i < N; i += SB) {
                float v = scache[i];
                if (v > SCORE_TH && binOf1(v) == piv1) atomicAdd(&S2[binOf2(v)], 1);
            }
            __syncthreads();
            suffix512_512(S2, wsum, wafter, t, lane, wid);
            const int need = target - above;
            if (S2[t] >= need && (t == NBINS2 - 1 || S2[t + 1] < need)) s_piv2 = t;
            __syncthreads();
            piv2 = s_piv2;
            cnt  = above + S2[piv2];
            if (cnt > KCAP) {
                if (t == 0) g_flag[bc] = 1;
                doneEarly = true;
            }
        }

        if (!doneEarly) {
            for (int i = t; i < N; i += SB) {
                float v = scache[i];
                if (v > SCORE_TH) {
                    int b1v = binOf1(v);
                    if (b1v > piv1 || (b1v == piv1 && (!use2 || binOf2(v) >= piv2))) {
                        int pos = atomicAdd(&s_ctr, 1);
                        key[pos] = packKey(v, (unsigned)i);
                    }
                }
            }
            for (int w = t; w < KCAP * (KCAP / 32); w += SB)
                ((unsigned*)suppRow)[w] = 0u;
            __syncthreads();

            if (t < KCAP) {
                unsigned long long k = key[t];
                if (k) {
                    int r = 0;
                    #pragma unroll 8
                    for (int j = 0; j < KCAP; j++) r += (key[j] > k);
                    skey[r] = k;
                }
            }
            __syncthreads();

            if (t < cnt) {
                float4 v = bp[keyIdx(skey[t])];
                cbox[t]  = v;
                carea[t] = (v.z - v.x) * (v.w - v.y);
            }
            __syncthreads();

            {
                const int tot = cnt * cnt;
                for (int p = t; p < tot; p += SB) {
                    int i = p / cnt, j = p - i * cnt;
                    if (j < i) {
                        float4 bi = cbox[i], bj = cbox[j];
                        float ix1 = fmaxf(bi.x, bj.x), iy1 = fmaxf(bi.y, bj.y);
                        float ix2 = fminf(bi.z, bj.z), iy2 = fminf(bi.w, bj.w);
                        float dx = fmaxf(ix2 - ix1, 0.f), dy = fmaxf(iy2 - iy1, 0.f);
                        float inter = dx * dy;
                        float u = fmaxf(carea[i] + carea[j] - inter, 1e-8f);
                        if (iouGtHalf(inter, u))
                            atomicOr(&suppRow[i][j >> 5], 1u << (j & 31));
                    }
                }
            }
            __syncthreads();

            if (t < 32) {
                unsigned keptw = 0;
                int kept = 0;
                for (int i = 0; i < cnt && kept < MAXDET; i++) {
                    unsigned r = (lane < KCAP / 32) ? suppRow[i][lane] : 0u;
                    bool hit = (r & keptw) != 0u;
                    if (!__any_sync(0xFFFFFFFFu, hit)) {
                        if (lane == (i >> 5)) keptw |= 1u << (i & 31);
                        if (lane == 0) keptIdx[kept] = (short)i;
                        kept++;
                    }
                }
                if (lane == 0) {
                    s_kept = kept;
                    if (kept < MAXDET && total > cnt) g_flag[bc] = 1;
                }
            }
            __syncthreads();
            const int kept = s_kept;
            if (t < kept) {
                int i = keptIdx[t];
                g_sc[base + t] = keyScore(skey[i]);
                g_bx[base + t] = cbox[i];
            }
            if (kept < MAXDET && total <= cnt) {
                for (int mm = kept + t; mm < MAXDET; mm += SB) g_sc[base + mm] = NEG;
            }
        }
    }

    // =============== ticket: last block of image b runs topk =================
    __syncthreads();
    __threadfence();
    if (t == 0) {
        unsigned int old = atomicAdd(&g_ticket[b], 1u);
        s_last = ((old % (unsigned)C) == (unsigned)(C - 1)) ? 1 : 0;
    }
    __syncthreads();
    if (!s_last) return;
    __threadfence();

    // ------- Phase 0: exact NMS for flagged classes (cold; smem-based) -------
    {
        if (t == 0) s_ctr = 0;
        __syncthreads();
        if (t < C && g_flag[b * C + t]) {
            int p = atomicAdd(&s_ctr, 1);
            keptIdx[p] = (short)t;
        }
        __syncthreads();
        const int nflag = s_ctr;
        for (int f = 0; f < nflag; f++) {
            const int fc = keptIdx[f];
            const int fbase = (b * C + fc) * MAXDET;
            const float* fcp = g_tcls + ((size_t)(b * MAXC + fc)) * MAXN;
            // load thresholded scores into scache (destructive workspace)
            for (int i = t; i < N; i += SB) {
                float v = fcp[i];
                scache[i] = (v > SCORE_TH) ? v : NEG;
            }
            __syncthreads();
            bool done = false;
            for (int m = 0; m < MAXDET && !done; m++) {
                // block argmax over scache (no register arrays)
                unsigned long long kk = 0ULL;
                for (int i = t; i < N; i += SB) {
                    unsigned long long cand = packKey(scache[i], (unsigned)i);
                    if (cand > kk) kk = cand;
                }
                unsigned long long k = blockKeyMax512(kk, red);
                float bscore = keyScore(k);
                if (!(bscore > SCORE_TH)) {
                    for (int mm = m + t; mm < MAXDET; mm += SB) g_sc[fbase + mm] = NEG;
                    done = true;
                } else {
                    unsigned bidx = keyIdx(k);
                    float4 B0 = bp[bidx];
                    if (t == 0) { g_sc[fbase + m] = bscore; g_bx[fbase + m] = B0; }
                    float a1 = (B0.z - B0.x) * (B0.w - B0.y);
                    for (int i = t; i < N; i += SB) {
                        if (scache[i] > NEG * 0.5f) {   // still alive
                            float4 bb = bp[i];
                            float a2 = (bb.z - bb.x) * (bb.w - bb.y);
                            float ix1 = fmaxf(B0.x, bb.x), iy1 = fmaxf(B0.y, bb.y);
                            float ix2 = fminf(B0.z, bb.z), iy2 = fminf(B0.w, bb.w);
                            float inter = fmaxf(ix2 - ix1, 0.f) * fmaxf(iy2 - iy1, 0.f);
                            float u = fmaxf(a1 + a2 - inter, 1e-8f);
                            if (iouGtHalf(inter, u)) scache[i] = NEG;
                        }
                    }
                    __syncthreads();
                }
            }
            __syncthreads();
        }
    }

    // ----------------------------- Phase 1: topk -----------------------------
    const int CM = C * MAXDET;
    const float* sp = g_sc + b * CM;
    float* oBoxes  = out;
    float* oScores = out + (size_t)B * MAXDET * 4;
    float* oLabels = out + (size_t)B * MAXDET * 5;

    S[2 * t] = 0; S[2 * t + 1] = 0; S2[t] = 0;
    if (t < KCAP) { key[t] = 0ULL; skey[t] = 0ULL; }
    if (t == 0) s_ctr = 0;
    __syncthreads();
    for (int i = t; i < CM; i += SB) {
        float v = sp[i];
        if (v > SCORE_TH) atomicAdd(&S[binOf1(v)], 1);
    }
    __syncthreads();
    suffix1024_512(S, wsum, wafter, t, lane, wid);
    const int tkTotal = S[0];

    if (tkTotal == 0) {
        if (t < MAXDET) {
            float* ob = oBoxes + ((size_t)b * MAXDET + t) * 4;
            ob[0] = -1.f; ob[1] = -1.f; ob[2] = -1.f; ob[3] = -1.f;
            oScores[b * MAXDET + t] = -1.f;
            oLabels[b * MAXDET + t] = -1.f;
        }
        return;
    }

    const int target = tkTotal < MAXDET ? tkTotal : MAXDET;
    #pragma unroll
    for (int h = 0; h < 2; h++) {
        int p = t + h * SB;
        if (S[p] >= target && (p == NBINS1 - 1 || S[p + 1] < target)) s_piv1 = p;
    }
    __syncthreads();
    const int piv1 = s_piv1;
    const int cnt1 = S[piv1];
    const int above = (piv1 + 1 < NBINS1) ? S[piv1 + 1] : 0;
    const bool use2 = (cnt1 > KCAP);
    int piv2 = 0;
    int cnt  = cnt1;
    if (use2) {
        for (int i = t; i < CM; i += SB) {
            float v = sp[i];
            if (v > SCORE_TH && binOf1(v) == piv1) atomicAdd(&S2[binOf2(v)], 1);
        }
        __syncthreads();
        suffix512_512(S2, wsum, wafter, t, lane, wid);
        const int need = target - above;
        if (S2[t] >= need && (t == NBINS2 - 1 || S2[t + 1] < need)) s_piv2 = t;
        __syncthreads();
        piv2 = s_piv2;
        cnt  = above + S2[piv2];
    }

    if (cnt > KCAP) {
        // exact iterative top-100 over scache copy (guaranteed cold path)
        for (int i = t; i < CM; i += SB) scache[i] = sp[i];
        __syncthreads();
        for (int r = 0; r < MAXDET; r++) {
            unsigned long long kk = 0ULL;
            for (int i = t; i < CM; i += SB) {
                float v = scache[i];
                if (v > SCORE_TH) {
                    unsigned long long cand = packKey(v, (unsigned)i);
                    if (cand > kk) kk = cand;
                }
            }
            unsigned long long k = blockKeyMax512(kk, red);
            if (k != 0ULL) {
                unsigned idx = keyIdx(k);
                if (t == (int)(idx % SB)) scache[idx] = NEG;   // one owner clears
            }
            __syncthreads();
            if (t == 0) {
                float scv = keyScore(k);
                unsigned idx = keyIdx(k);
                float bx = -1.f, by = -1.f, bz = -1.f, bw = -1.f, so = -1.f, lab = -1.f;
                if (k != 0ULL && scv > SCORE_TH) {
                    float4 bb = g_bx[b * CM + idx];
                    bx = bb.x; by = bb.y; bz = bb.z; bw = bb.w;
                    so = scv; lab = (float)(idx / MAXDET);
                }
                float* ob = oBoxes + ((size_t)b * MAXDET + r) * 4;
                ob[0] = bx; ob[1] = by; ob[2] = bz; ob[3] = bw;
                oScores[b * MAXDET + r] = so;
                oLabels[b * MAXDET + r] = lab;
            }
        }
        return;
    }

    for (int i = t; i < CM; i += SB) {
        float v = sp[i];
        if (v > SCORE_TH) {
            int b1v = binOf1(v);
            if (b1v > piv1 || (b1v == piv1 && (!use2 || binOf2(v) >= piv2))) {
                int pos = atomicAdd(&s_ctr, 1);
                key[pos] = packKey(v, (unsigned)i);
            }
        }
    }
    __syncthreads();
    if (t < KCAP) {
        unsigned long long k = key[t];
        if (k) {
            int r = 0;
            #pragma unroll 8
            for (int j = 0; j < KCAP; j++) r += (key[j] > k);
            skey[r] = k;
        }
    }
    __syncthreads();
    if (t < MAXDET) {
        float bx = -1.f, by = -1.f, bz = -1.f, bw = -1.f, so = -1.f, lab = -1.f;
        if (t < cnt) {
            unsigned long long k = skey[t];
            float scv = keyScore(k);
            unsigned idx = keyIdx(k);
            float4 bb = g_bx[b * CM + idx];
            bx = bb.x; by = bb.y; bz = bb.z; bw = bb.w;
            so = scv; lab = (float)(idx / MAXDET);
        }
        float* ob = oBoxes + ((size_t)b * MAXDET + t) * 4;
        ob[0] = bx; ob[1] = by; ob[2] = bz; ob[3] = bw;
        oScores[b * MAXDET + t] = so;
        oLabels[b * MAXDET + t] = lab;
    }
}

extern "C" void kernel_launch(void* const* d_in, const int* in_sizes, int n_in,
                              void* d_out, int out_size) {
    const float4* boxes = (const float4*)d_in[0];   // (B, N, 4) f32
    const float*  cls   = (const float*)d_in[1];    // (B, N, C) f32
    float*        out   = (float*)d_out;

    int B = out_size / (6 * MAXDET);
    if (B < 1) B = 1;
    int N = in_sizes[0] / (4 * B);
    int C = in_sizes[1] / (B * N);
    if (N > MAXN || C > MAXC || B > MAXB || C * MAXDET > MAXN) return;

    const int selSmem = N * (int)sizeof(float);
    const int trSmem  = TROWS * (C | 1) * (int)sizeof(float);
    cudaFuncSetAttribute(select_nms_kernel,
                         cudaFuncAttributeMaxDynamicSharedMemorySize, selSmem);
    cudaFuncSetAttribute(transpose_kernel,
                         cudaFuncAttributeMaxDynamicSharedMemorySize, trSmem);

    dim3 tgrid((N + TROWS - 1) / TROWS, B);
    transpose_kernel<<<tgrid, XB, trSmem>>>(cls, N, C);
    dim3 grid(C, B);
    select_nms_kernel<<<grid, SB, selSmem>>>(boxes, out, N, C, B);
}

// round 17
// speedup vs baseline: 1.0957x; 1.0957x over previous
#include <cuda_runtime.h>
#include <math.h>

#define NEG        (-1.0e9f)
#define SCORE_TH   (0.05f)
#define MAXDET     100

#define NBINS1     1024               // (bits>>16)-MINB16; score 1.0 -> bin 564
#define NBINS2     512                // bits[7:16) within one level-1 bin
#define MINB16     15692              // bits(0.05f) >> 16
#define KCAP       256                // candidate capacity (select & topk)
#define TARGET     160                // select candidate target (>= MAXDET + margin)
#define SB         512                // select block
#define TK         1024               // topk block
#define FIT        10                 // N <= 1024*10 (inline fallback items)
#define TKITEMS    8                  // C*M <= 1024*8
#define TROWS      16                 // transpose tile rows
#define XB         256                // transpose block

#define MAXB       4
#define MAXC       96
#define MAXN       10240

__device__ float  g_tcls[MAXB * MAXC * MAXN];   // (B,C,N) transposed scores
__device__ float  g_sc[MAXB * MAXC * MAXDET];
__device__ float4 g_bx[MAXB * MAXC * MAXDET];
__device__ int    g_flag[MAXB * MAXC];

__device__ __forceinline__ unsigned long long packKey(float s, unsigned idx) {
    unsigned u = __float_as_uint(s);
    u = (u & 0x80000000u) ? ~u : (u | 0x80000000u);
    return ((unsigned long long)u << 32) | (unsigned)(~idx);
}
__device__ __forceinline__ float keyScore(unsigned long long k) {
    unsigned u = (unsigned)(k >> 32);
    u = (u & 0x80000000u) ? (u & 0x7FFFFFFFu) : ~u;
    return __uint_as_float(u);
}
__device__ __forceinline__ unsigned keyIdx(unsigned long long k) {
    return ~(unsigned)(k & 0xFFFFFFFFu);
}
// exact equivalent of RN(inter/u) > 0.5 for u >= ~1 (areas >= 1 here)
__device__ __forceinline__ bool iouGtHalf(float inter, float u) {
    return fmaf(-0.5f, u, inter) > 2.9802322387695312e-08f * u;
}
__device__ __forceinline__ int binOf1(float sc) {   // sc > 0.05
    int b = (int)(__float_as_uint(sc) >> 16) - MINB16;
    return b > (NBINS1 - 1) ? (NBINS1 - 1) : b;
}
__device__ __forceinline__ int binOf2(float sc) {
    return (int)((__float_as_uint(sc) >> 7) & 0x1FFu);
}

// ---- 512-thread helpers (select) ----
__device__ __forceinline__ void suffix1024_512(int* S, int* wsum, int* wafter,
                                               int t, int lane, int wid) {
    int b0 = S[2 * t], b1 = S[2 * t + 1];
    int s = b0 + b1;
    #pragma unroll
    for (int o = 1; o < 32; o <<= 1) {
        int u = __shfl_down_sync(0xFFFFFFFFu, s, o);
        if (lane + o < 32) s += u;
    }
    if (lane == 0) wsum[wid] = s;
    __syncthreads();
    if (t < 32) {
        int v = (t < 16) ? wsum[t] : 0;
        #pragma unroll
        for (int o = 1; o < 16; o <<= 1) {
            int u = __shfl_down_sync(0xFFFFFFFFu, v, o);
            if (t + o < 16) v += u;
        }
        if (t < 16) wafter[t] = v - wsum[t];
    }
    __syncthreads();
    int T = s + wafter[wid];
    S[2 * t] = T;
    S[2 * t + 1] = T - b0;
    __syncthreads();
}
__device__ __forceinline__ void suffix512_512(int* S2, int* wsum, int* wafter,
                                              int t, int lane, int wid) {
    int s = S2[t];
    #pragma unroll
    for (int o = 1; o < 32; o <<= 1) {
        int u = __shfl_down_sync(0xFFFFFFFFu, s, o);
        if (lane + o < 32) s += u;
    }
    if (lane == 0) wsum[wid] = s;
    __syncthreads();
    if (t < 32) {
        int v = (t < 16) ? wsum[t] : 0;
        #pragma unroll
        for (int o = 1; o < 16; o <<= 1) {
            int u = __shfl_down_sync(0xFFFFFFFFu, v, o);
            if (t + o < 16) v += u;
        }
        if (t < 16) wafter[t] = v - wsum[t];
    }
    __syncthreads();
    S2[t] = s + wafter[wid];
    __syncthreads();
}

// ---- 1024-thread helpers (topk) ----
__device__ __forceinline__ void suffix1024_1024(int* S, int* wsum, int* wafter,
                                                int t, int lane, int wid) {
    int s = S[t];
    #pragma unroll
    for (int o = 1; o < 32; o <<= 1) {
        int u = __shfl_down_sync(0xFFFFFFFFu, s, o);
        if (lane + o < 32) s += u;
    }
    if (lane == 0) wsum[wid] = s;
    __syncthreads();
    if (t < 32) {
        int v = wsum[t];
        #pragma unroll
        for (int o = 1; o < 32; o <<= 1) {
            int u = __shfl_down_sync(0xFFFFFFFFu, v, o);
            if (t + o < 32) v += u;
        }
        wafter[t] = v - wsum[t];
    }
    __syncthreads();
    S[t] = s + wafter[wid];
    __syncthreads();
}
__device__ __forceinline__ void suffix512_1024(int* S2, int* wsum, int* wafter,
                                               int t, int lane, int wid) {
    int s = 0;
    if (t < NBINS2) {
        s = S2[t];
        #pragma unroll
        for (int o = 1; o < 32; o <<= 1) {
            int u = __shfl_down_sync(0xFFFFFFFFu, s, o);
            if (lane + o < 32) s += u;
        }
        if (lane == 0) wsum[wid] = s;
    }
    __syncthreads();
    if (t < 32) {
        int v = (t < 16) ? wsum[t] : 0;
        #pragma unroll
        for (int o = 1; o < 16; o <<= 1) {
            int u = __shfl_down_sync(0xFFFFFFFFu, v, o);
            if (t + o < 16) v += u;
        }
        if (t < 16) wafter[t] = v - wsum[t];
    }
    __syncthreads();
    if (t < NBINS2) S2[t] = s + wafter[wid];
    __syncthreads();
}
__device__ __forceinline__ unsigned long long blockKeyMax1024(unsigned long long k,
                                                              unsigned long long* red) {
    int lane = threadIdx.x & 31;
    int wid  = threadIdx.x >> 5;
    #pragma unroll
    for (int o = 16; o > 0; o >>= 1) {
        unsigned long long other = __shfl_down_sync(0xFFFFFFFFu, k, o);
        if (other > k) k = other;
    }
    if (lane == 0) red[wid] = k;
    __syncthreads();
    if (wid == 0) {
        unsigned long long v = red[lane];
        #pragma unroll
        for (int o = 16; o > 0; o >>= 1) {
            unsigned long long other = __shfl_down_sync(0xFFFFFFFFu, v, o);
            if (other > v) v = other;
        }
        if (lane == 0) red[32] = v;
    }
    __syncthreads();
    unsigned long long r = red[32];
    __syncthreads();
    return r;
}

// ======= Kernel 0: transpose (B,N,C)->(B,C,N), float4 both sides =============
__global__ void __launch_bounds__(XB)
transpose_kernel(const float* __restrict__ cls, int N, int C) {
    extern __shared__ float tile[];                 // TROWS * RS floats, RS odd
    const int RS = C | 1;                           // odd row stride: bank-safe
    const int b  = blockIdx.y;
    const int i0 = blockIdx.x * TROWS;
    const int t  = threadIdx.x;
    int rows = N - i0; if (rows > TROWS) rows = TROWS;
    const int n_e = rows * C;
    const float* src = cls + (size_t)b * N * C + (size_t)i0 * C;

    if ((C & 3) == 0) {
        const float4* s4 = (const float4*)src;
        const int n4 = n_e >> 2;
        const int C4 = C >> 2;
        for (int e = t; e < n4; e += XB) {
            float4 v = s4[e];
            int r = e / C4, c0 = (e - r * C4) << 2;
            float* dst = tile + r * RS + c0;
            dst[0] = v.x; dst[1] = v.y; dst[2] = v.z; dst[3] = v.w;
        }
    } else {
        for (int e = t; e < n_e; e += XB) {
            int r = e / C, c = e - r * C;
            tile[r * RS + c] = src[e];
        }
    }
    __syncthreads();

    // store: float4 along r; e = c * r4cnt + r4 (r4cnt=4 full tile -> warp = 8
    // classes x 4 quads = 64B coalesced segments; latency-bound so occ wins)
    const int r4cnt = rows >> 2;
    const int n_out4 = C * r4cnt;
    for (int e = t; e < n_out4; e += XB) {
        int c2  = e / r4cnt;
        int rr4 = e - c2 * r4cnt;
        int r0 = rr4 << 2;
        const float* srcw = tile + r0 * RS + c2;
        float4 v;
        v.x = srcw[0];
        v.y = srcw[RS];
        v.z = srcw[2 * RS];
        v.w = srcw[3 * RS];
        *(float4*)&g_tcls[((size_t)(b * MAXC + c2)) * MAXN + i0 + r0] = v;
    }
    const int rrem0 = r4cnt << 2;
    if (rrem0 < rows) {
        const int n_rem = C * (rows - rrem0);
        for (int e = t; e < n_rem; e += XB) {
            int c = e / (rows - rrem0), r = rrem0 + (e - c * (rows - rrem0));
            g_tcls[((size_t)(b * MAXC + c)) * MAXN + i0 + r] = tile[r * RS + c];
        }
    }
}

// == Kernel 1: radix select + rank-scatter + bitmask greedy NMS ===============
__global__ void __launch_bounds__(SB, 2)
select_nms_kernel(const float4* __restrict__ boxes, int N, int C) {
    extern __shared__ float       scache[];          // N floats (score cache)
    __shared__ int                S[NBINS1];
    __shared__ int                S2[NBINS2];
    __shared__ unsigned long long key[KCAP];
    __shared__ unsigned long long skey[KCAP];
    __shared__ float4             cbox[KCAP];
    __shared__ float              carea[KCAP];
    __shared__ unsigned           suppRow[KCAP][KCAP / 32];   // 8 KB lower-tri bits
    __shared__ short              keptIdx[MAXDET];
    __shared__ int                wsum[16], wafter[16];
    __shared__ int                s_piv1, s_piv2, s_ctr, s_kept;

    const int c = blockIdx.x;
    const int b = blockIdx.y;
    const int t = threadIdx.x;
    const int lane = t & 31, wid = t >> 5;
    const int bc = b * C + c;
    const int base = bc * MAXDET;
    const float*  cp  = g_tcls + ((size_t)(b * MAXC + c)) * MAXN;
    const float4* cp4 = (const float4*)cp;
    const float4* bp  = boxes + (size_t)b * N;
    float4* sc4 = (float4*)scache;
    const int N4 = N >> 2;

    S[2 * t] = 0; S[2 * t + 1] = 0; S2[t] = 0;
    if (t < KCAP) { key[t] = 0ULL; skey[t] = 0ULL; }
    if (t == 0) { s_ctr = 0; g_flag[bc] = 0; }
    __syncthreads();

    for (int i = t; i < N4; i += SB) {
        float4 v = cp4[i];
        sc4[i] = v;
        if (v.x > SCORE_TH) atomicAdd(&S[binOf1(v.x)], 1);
        if (v.y > SCORE_TH) atomicAdd(&S[binOf1(v.y)], 1);
        if (v.z > SCORE_TH) atomicAdd(&S[binOf1(v.z)], 1);
        if (v.w > SCORE_TH) atomicAdd(&S[binOf1(v.w)], 1);
    }
    for (int i = 4 * N4 + t; i < N; i += SB) {
        float v = cp[i];
        scache[i] = v;
        if (v > SCORE_TH) atomicAdd(&S[binOf1(v)], 1);
    }
    __syncthreads();
    suffix1024_512(S, wsum, wafter, t, lane, wid);

    const int total = S[0];
    if (total == 0) {
        for (int mm = t; mm < MAXDET; mm += SB) g_sc[base + mm] = NEG;
        return;
    }
    const int target = total < TARGET ? total : TARGET;
    #pragma unroll
    for (int h = 0; h < 2; h++) {
        int p = t + h * SB;
        if (S[p] >= target && (p == NBINS1 - 1 || S[p + 1] < target)) s_piv1 = p;
    }
    __syncthreads();
    const int piv1 = s_piv1;
    const int cnt1 = S[piv1];
    const int above = (piv1 + 1 < NBINS1) ? S[piv1 + 1] : 0;
    const bool use2 = (cnt1 > KCAP);
    int piv2 = 0;
    int cnt  = cnt1;

    if (use2) {
        for (int i = t; i < N; i += SB) {
            float v = scache[i];
            if (v > SCORE_TH && binOf1(v) == piv1) atomicAdd(&S2[binOf2(v)], 1);
        }
        __syncthreads();
        suffix512_512(S2, wsum, wafter, t, lane, wid);
        const int need = target - above;
        if (S2[t] >= need && (t == NBINS2 - 1 || S2[t + 1] < need)) s_piv2 = t;
        __syncthreads();
        piv2 = s_piv2;
        cnt  = above + S2[piv2];
        if (cnt > KCAP) { if (t == 0) g_flag[bc] = 1; return; }
    }

    for (int i = t; i < N; i += SB) {
        float v = scache[i];
        if (v > SCORE_TH) {
            int b1v = binOf1(v);
            if (b1v > piv1 || (b1v == piv1 && (!use2 || binOf2(v) >= piv2))) {
                int pos = atomicAdd(&s_ctr, 1);
                key[pos] = packKey(v, (unsigned)i);
            }
        }
    }
    for (int w = t; w < KCAP * (KCAP / 32); w += SB)
        ((unsigned*)suppRow)[w] = 0u;
    __syncthreads();

    if (t < KCAP) {
        unsigned long long k = key[t];
        if (k) {
            int r = 0;
            #pragma unroll 8
            for (int j = 0; j < KCAP; j++) r += (key[j] > k);
            skey[r] = k;
        }
    }
    __syncthreads();

    if (t < cnt) {
        float4 v = bp[keyIdx(skey[t])];
        cbox[t]  = v;
        carea[t] = (v.z - v.x) * (v.w - v.y);
    }
    __syncthreads();

    {
        const int tot = cnt * cnt;
        for (int p = t; p < tot; p += SB) {
            int i = p / cnt, j = p - i * cnt;
            if (j < i) {
                float4 bi = cbox[i], bj = cbox[j];
                float ix1 = fmaxf(bi.x, bj.x), iy1 = fmaxf(bi.y, bj.y);
                float ix2 = fminf(bi.z, bj.z), iy2 = fminf(bi.w, bj.w);
                float dx = fmaxf(ix2 - ix1, 0.f), dy = fmaxf(iy2 - iy1, 0.f);
                float inter = dx * dy;
                float u = fmaxf(carea[i] + carea[j] - inter, 1e-8f);
                if (iouGtHalf(inter, u))
                    atomicOr(&suppRow[i][j >> 5], 1u << (j & 31));
            }
        }
    }
    __syncthreads();

    if (t < 32) {
        unsigned keptw = 0;
        int kept = 0;
        for (int i = 0; i < cnt && kept < MAXDET; i++) {
            unsigned r = (lane < KCAP / 32) ? suppRow[i][lane] : 0u;
            bool hit = (r & keptw) != 0u;
            if (!__any_sync(0xFFFFFFFFu, hit)) {
                if (lane == (i >> 5)) keptw |= 1u << (i & 31);
                if (lane == 0) keptIdx[kept] = (short)i;
                kept++;
            }
        }
        if (lane == 0) {
            s_kept = kept;
            if (kept < MAXDET && total > cnt) g_flag[bc] = 1;
        }
    }
    __syncthreads();
    const int kept = s_kept;
    if (t < kept) {
        int i = keptIdx[t];
        g_sc[base + t] = keyScore(skey[i]);
        g_bx[base + t] = cbox[i];
    }
    if (kept < MAXDET && total <= cnt) {
        for (int mm = kept + t; mm < MAXDET; mm += SB) g_sc[base + mm] = NEG;
    }
}

// === Kernel 2: per-image topk (1024 thr) + inline exact NMS for flagged ======
__global__ void __launch_bounds__(TK)
topk_kernel(const float4* __restrict__ boxes, float* __restrict__ out,
            int N, int C, int B) {
    __shared__ int                S[NBINS1];
    __shared__ int                S2[NBINS2];
    __shared__ unsigned long long key[KCAP];
    __shared__ unsigned long long skey[KCAP];
    __shared__ int                wsum[32], wafter[32];
    __shared__ unsigned long long red[33];
    __shared__ int                s_piv1, s_piv2, s_ctr, s_nflag;
    __shared__ short              flagged[MAXC];

    const int b = blockIdx.x;
    const int t = threadIdx.x;
    const int lane = t & 31, wid = t >> 5;
    const int CM = C * MAXDET;

    if (t == 0) s_nflag = 0;
    __syncthreads();
    if (t < C && g_flag[b * C + t]) {
        int p = atomicAdd(&s_nflag, 1);
        flagged[p] = (short)t;
    }
    __syncthreads();
    const int nflag = s_nflag;
    for (int f = 0; f < nflag; f++) {
        const int c = flagged[f];
        const int bc = b * C + c;
        const int base = bc * MAXDET;
        const float4* bp = boxes + (size_t)b * N;
        const float*  cp = g_tcls + ((size_t)(b * MAXC + c)) * MAXN;
        float s[FIT], a2[FIT];
        #pragma unroll
        for (int j = 0; j < FIT; j++) {
            int i = t + j * TK;
            if (i < N) {
                float4 b4 = bp[i];
                a2[j] = (b4.z - b4.x) * (b4.w - b4.y);
                float v = cp[i];
                s[j] = (v > SCORE_TH) ? v : NEG;
            } else { a2[j] = 0.f; s[j] = -3.402823466e+38f; }
        }
        bool done = false;
        for (int m = 0; m < MAXDET && !done; m++) {
            float bm = s[0]; int bj = 0;
            #pragma unroll
            for (int j = 1; j < FIT; j++) if (s[j] > bm) { bm = s[j]; bj = j; }
            unsigned long long k = blockKeyMax1024(packKey(bm, (unsigned)(t + bj * TK)), red);
            float bscore = keyScore(k);
            if (!(bscore > SCORE_TH)) {
                for (int mm = m + t; mm < MAXDET; mm += TK) g_sc[base + mm] = NEG;
                done = true;
            } else {
                unsigned bidx = keyIdx(k);
                float4 B0 = bp[bidx];
                if (t == 0) { g_sc[base + m] = bscore; g_bx[base + m] = B0; }
                float a1 = (B0.z - B0.x) * (B0.w - B0.y);
                #pragma unroll
                for (int j = 0; j < FIT; j++) {
                    int i = t + j * TK;
                    float4 bb = (i < N) ? bp[i] : make_float4(0.f, 0.f, 0.f, 0.f);
                    float ix1 = fmaxf(B0.x, bb.x), iy1 = fmaxf(B0.y, bb.y);
                    float ix2 = fminf(B0.z, bb.z), iy2 = fminf(B0.w, bb.w);
                    float inter = fmaxf(ix2 - ix1, 0.f) * fmaxf(iy2 - iy1, 0.f);
                    float u = fmaxf(a1 + a2[j] - inter, 1e-8f);
                    if (iouGtHalf(inter, u)) s[j] = NEG;
                }
            }
        }
        __syncthreads();
    }

    const float* sp = g_sc + b * CM;
    float* oBoxes  = out;
    float* oScores = out + (size_t)B * MAXDET * 4;
    float* oLabels = out + (size_t)B * MAXDET * 5;

    float sc[TKITEMS];
    #pragma unroll
    for (int j = 0; j < TKITEMS; j++) {
        int i = t + j * TK;
        sc[j] = (i < CM) ? sp[i] : NEG;
    }

    S[t] = 0;
    if (t < NBINS2) S2[t] = 0;
    if (t < KCAP) { key[t] = 0ULL; skey[t] = 0ULL; }
    if (t == 0) s_ctr = 0;
    __syncthreads();
    #pragma unroll
    for (int j = 0; j < TKITEMS; j++)
        if (sc[j] > SCORE_TH) atomicAdd(&S[binOf1(sc[j])], 1);
    __syncthreads();
    suffix1024_1024(S, wsum, wafter, t, lane, wid);
    const int total = S[0];

    if (total == 0) {
        if (t < MAXDET) {
            float* ob = oBoxes + ((size_t)b * MAXDET + t) * 4;
            ob[0] = -1.f; ob[1] = -1.f; ob[2] = -1.f; ob[3] = -1.f;
            oScores[b * MAXDET + t] = -1.f;
            oLabels[b * MAXDET + t] = -1.f;
        }
        return;
    }

    const int target = total < MAXDET ? total : MAXDET;
    if (S[t] >= target && (t == NBINS1 - 1 || S[t + 1] < target)) s_piv1 = t;
    __syncthreads();
    const int piv1 = s_piv1;
    const int cnt1 = S[piv1];
    const int above = (piv1 + 1 < NBINS1) ? S[piv1 + 1] : 0;
    const bool use2 = (cnt1 > KCAP);
    int piv2 = 0;
    int cnt  = cnt1;
    if (use2) {
        #pragma unroll
        for (int j = 0; j < TKITEMS; j++)
            if (sc[j] > SCORE_TH && binOf1(sc[j]) == piv1)
                atomicAdd(&S2[binOf2(sc[j])], 1);
        __syncthreads();
        suffix512_1024(S2, wsum, wafter, t, lane, wid);
        const int need = target - above;
        if (t < NBINS2 && S2[t] >= need && (t == NBINS2 - 1 || S2[t + 1] < need)) s_piv2 = t;
        __syncthreads();
        piv2 = s_piv2;
        cnt  = above + S2[piv2];
    }

    if (cnt > KCAP) {
        unsigned long long kreg[TKITEMS];
        #pragma unroll
        for (int j = 0; j < TKITEMS; j++) {
            int i = t + j * TK;
            kreg[j] = (i < CM && sc[j] > SCORE_TH) ? packKey(sc[j], (unsigned)i) : 0ULL;
        }
        for (int r = 0; r < MAXDET; r++) {
            unsigned long long k0 = kreg[0];
            #pragma unroll
            for (int j = 1; j < TKITEMS; j++) if (kreg[j] > k0) k0 = kreg[j];
            unsigned long long k = blockKeyMax1024(k0, red);
            #pragma unroll
            for (int j = 0; j < TKITEMS; j++) if (kreg[j] == k) kreg[j] = 0ULL;
            if (t == 0) {
                float scv = keyScore(k);
                unsigned idx = keyIdx(k);
                float bx = -1.f, by = -1.f, bz = -1.f, bw = -1.f, so = -1.f, lab = -1.f;
                if (k != 0ULL && scv > SCORE_TH) {
                    float4 bb = g_bx[b * CM + idx];
                    bx = bb.x; by = bb.y; bz = bb.z; bw = bb.w;
                    so = scv; lab = (float)(idx / MAXDET);
                }
                float* ob = oBoxes + ((size_t)b * MAXDET + r) * 4;
                ob[0] = bx; ob[1] = by; ob[2] = bz; ob[3] = bw;
                oScores[b * MAXDET + r] = so;
                oLabels[b * MAXDET + r] = lab;
            }
        }
        return;
    }

    #pragma unroll
    for (int j = 0; j < TKITEMS; j++) {
        float v = sc[j];
        if (v > SCORE_TH) {
            int b1v = binOf1(v);
            if (b1v > piv1 || (b1v == piv1 && (!use2 || binOf2(v) >= piv2))) {
                int pos = atomicAdd(&s_ctr, 1);
                key[pos] = packKey(v, (unsigned)(t + j * TK));
            }
        }
    }
    __syncthreads();
    if (t < KCAP) {
        unsigned long long k = key[t];
        if (k) {
            int r = 0;
            #pragma unroll 8
            for (int j = 0; j < KCAP; j++) r += (key[j] > k);
            skey[r] = k;
        }
    }
    __syncthreads();
    if (t < MAXDET) {
        float bx = -1.f, by = -1.f, bz = -1.f, bw = -1.f, so = -1.f, lab = -1.f;
        if (t < cnt) {
            unsigned long long k = skey[t];
            float scv = keyScore(k);
            unsigned idx = keyIdx(k);
            float4 bb = g_bx[b * CM + idx];
            bx = bb.x; by = bb.y; bz = bb.z; bw = bb.w;
            so = scv; lab = (float)(idx / MAXDET);
        }
        float* ob = oBoxes + ((size_t)b * MAXDET + t) * 4;
        ob[0] = bx; ob[1] = by; ob[2] = bz; ob[3] = bw;
        oScores[b * MAXDET + t] = so;
        oLabels[b * MAXDET + t] = lab;
    }
}

extern "C" void kernel_launch(void* const* d_in, const int* in_sizes, int n_in,
                              void* d_out, int out_size) {
    const float4* boxes = (const float4*)d_in[0];   // (B, N, 4) f32
    const float*  cls   = (const float*)d_in[1];    // (B, N, C) f32
    float*        out   = (float*)d_out;

    int B = out_size / (6 * MAXDET);
    if (B < 1) B = 1;
    int N = in_sizes[0] / (4 * B);
    int C = in_sizes[1] / (B * N);
    if (N > MAXN || C > MAXC || B > MAXB ||
        N > TK * FIT || C * MAXDET > TK * TKITEMS) return;

    const int selSmem = N * (int)sizeof(float);
    const int trSmem  = TROWS * (C | 1) * (int)sizeof(float);
    cudaFuncSetAttribute(select_nms_kernel,
                         cudaFuncAttributeMaxDynamicSharedMemorySize, selSmem);
    cudaFuncSetAttribute(transpose_kernel,
                         cudaFuncAttributeMaxDynamicSharedMemorySize, trSmem);

    dim3 tgrid((N + TROWS - 1) / TROWS, B);
    transpose_kernel<<<tgrid, XB, trSmem>>>(cls, N, C);
    dim3 grid(C, B);
    select_nms_kernel<<<grid, SB, selSmem>>>(boxes, N, C);
    topk_kernel<<<B, TK>>>(boxes, out, N, C, B);
}